// round 15
// baseline (speedup 1.0000x reference)
#include <cuda_runtime.h>
#include <cuda_fp16.h>
#include <cstdint>

#define Bb 128
#define Ff 8
#define Kk 256
#define Dd 256
#define Hh 256
#define HFF 512
#define CAND_CAP 512
#define DELTA 0.75f
#define NC 16
#define CHUNK2 18432        // 128 n-rows x 144B (k64 fp16 + 16B pad)
typedef unsigned long long ull;

// ---------------- device scratch ---------------------------------------------
__device__ float g_h0 [Kk*Hh];
__device__ float g_g  [Kk*Hh];
__device__ float g_t  [Bb*Ff*Hh];
__device__ float g_A1g[Kk*HFF];
__device__ float g_A2g[Kk*HFF];
__device__ float g_A1t[Bb*Ff*HFF];
__device__ float g_A2t[Bb*Ff*HFF];
__device__ float g_Og [Kk*Dd];
__device__ float g_Ot [Bb*Ff*Dd];
__device__ float g_M12[HFF*HFF];
__device__ float g_M1o[HFF*Dd];
__device__ float g_M2o[HFF*Dd];
__device__ float g_bu2[HFF];
__device__ float g_bo [Dd];
__device__ float g_dists[Bb*Ff*Kk];
__device__ __align__(128) char g_M12p[32*CHUNK2];
__device__ __align__(128) char g_M1op[16*CHUNK2];
__device__ __align__(128) char g_M2op[16*CHUNK2];
__device__ int  g_cnum[Bb];
__device__ int  g_clist[Bb*CAND_CAP];
__device__ ull  g_best[Bb];

// ---------------- helpers ------------------------------------------------------
__device__ __forceinline__ uint32_t smem_to_u32(const void* p) {
    uint32_t a;
    asm("{ .reg .u64 t; cvta.to.shared.u64 t, %1; cvt.u32.u64 %0, t; }" : "=r"(a) : "l"(p));
    return a;
}
__device__ __forceinline__ void mma_f16(float* c, uint32_t a0, uint32_t a1, uint32_t a2,
                                        uint32_t a3, uint32_t b0, uint32_t b1)
{
    asm volatile(
        "mma.sync.aligned.m16n8k16.row.col.f32.f16.f16.f32 "
        "{%0,%1,%2,%3}, {%4,%5,%6,%7}, {%8,%9}, {%0,%1,%2,%3};"
        : "+f"(c[0]), "+f"(c[1]), "+f"(c[2]), "+f"(c[3])
        : "r"(a0), "r"(a1), "r"(a2), "r"(a3), "r"(b0), "r"(b1));
}
__device__ __forceinline__ void ldsm4(uint32_t& r0, uint32_t& r1, uint32_t& r2, uint32_t& r3,
                                      uint32_t addr)
{
    asm volatile("ldmatrix.sync.aligned.m8n8.x4.shared.b16 {%0,%1,%2,%3}, [%4];"
        : "=r"(r0), "=r"(r1), "=r"(r2), "=r"(r3) : "r"(addr));
}
#define MBARRIER_INIT(addr, cnt) \
    asm volatile("mbarrier.init.shared.b64 [%0], %1;" :: "r"((uint32_t)(addr)), "r"((uint32_t)(cnt)) : "memory")
#define MBARRIER_ARRIVE(addr) \
    asm volatile("mbarrier.arrive.shared.b64 _, [%0];" :: "r"((uint32_t)(addr)) : "memory")
#define MBARRIER_EXPECT_TX(addr, tx) \
    asm volatile("mbarrier.arrive.expect_tx.shared.b64 _, [%0], %1;" :: "r"((uint32_t)(addr)), "r"((uint32_t)(tx)) : "memory")
#define MBARRIER_WAIT_PARITY(addr, par) do { \
    uint32_t _mb = (uint32_t)(addr); uint32_t _p = (uint32_t)(par); uint32_t _d; \
    asm volatile("{\n\t.reg .pred p;\n\t" \
        "mbarrier.try_wait.parity.acquire.cta.shared::cta.b64 p, [%1], %2;\n\t" \
        "selp.b32 %0, 1, 0, p;\n\t}" : "=r"(_d) : "r"(_mb), "r"(_p) : "memory"); \
    if (!_d) { \
        asm volatile("{\n\t.reg .pred P1;\n\t" \
            "WL_%=:\n\t" \
            "mbarrier.try_wait.parity.acquire.cta.shared::cta.b64 P1, [%0], %1, 0x989680;\n\t" \
            "@P1 bra.uni WD_%=;\n\t" \
            "bra.uni WL_%=;\n\t" \
            "WD_%=:\n\t}" :: "r"(_mb), "r"(_p) : "memory"); \
    } } while (0)
__device__ __forceinline__ void bulk_copy(uint32_t dst_smem, const void* src, uint32_t bytes,
                                          uint32_t mbar)
{
    asm volatile(
        "cp.async.bulk.shared::cluster.global.mbarrier::complete_tx::bytes [%0], [%1], %2, [%3];"
        :: "r"(dst_smem), "l"(src), "r"(bytes), "r"(mbar) : "memory");
}

// ---------------- batched precompute --------------------------------------------
struct GJob { const float* A; const float* B; float* C; int M, N, K;
              const float* bias; const float* add; };
struct GBatch { GJob j[6]; };

__device__ __forceinline__ void sgemm64_body(
    const float* __restrict__ A, const float* __restrict__ B, float* __restrict__ C,
    int M, int N, int K, const float* __restrict__ bias, const float* __restrict__ add,
    float As[16][65], float Bs[16][64])
{
    const int m0 = blockIdx.y * 64, n0 = blockIdx.x * 64;
    const int tid = threadIdx.x, tx = tid & 15, ty = tid >> 4;
    float acc[4][4] = {};
    for (int k0 = 0; k0 < K; k0 += 16) {
        int ra = tid >> 2, ca = (tid & 3) * 4;
        float4 av = *(const float4*)(A + (size_t)(m0 + ra) * K + k0 + ca);
        As[ca+0][ra] = av.x; As[ca+1][ra] = av.y; As[ca+2][ra] = av.z; As[ca+3][ra] = av.w;
        int rb = tid >> 4, cb = (tid & 15) * 4;
        *(float4*)&Bs[rb][cb] = *(const float4*)(B + (size_t)(k0 + rb) * N + n0 + cb);
        __syncthreads();
        #pragma unroll
        for (int kk = 0; kk < 16; kk++) {
            float a0 = As[kk][ty*4+0], a1 = As[kk][ty*4+1];
            float a2 = As[kk][ty*4+2], a3 = As[kk][ty*4+3];
            float4 bv = *(float4*)&Bs[kk][tx*4];
            acc[0][0]+=a0*bv.x; acc[0][1]+=a0*bv.y; acc[0][2]+=a0*bv.z; acc[0][3]+=a0*bv.w;
            acc[1][0]+=a1*bv.x; acc[1][1]+=a1*bv.y; acc[1][2]+=a1*bv.z; acc[1][3]+=a1*bv.w;
            acc[2][0]+=a2*bv.x; acc[2][1]+=a2*bv.y; acc[2][2]+=a2*bv.z; acc[2][3]+=a2*bv.w;
            acc[3][0]+=a3*bv.x; acc[3][1]+=a3*bv.y; acc[3][2]+=a3*bv.z; acc[3][3]+=a3*bv.w;
        }
        __syncthreads();
    }
    #pragma unroll
    for (int i = 0; i < 4; i++)
        #pragma unroll
        for (int j = 0; j < 4; j++) {
            int m = m0 + ty*4 + i, n = n0 + tx*4 + j;
            float v = acc[i][j];
            if (bias) v += bias[n];
            if (add)  v += add[(size_t)m * N + n];
            C[(size_t)m * N + n] = v;
        }
}

__global__ __launch_bounds__(256) void stage1_kernel(
    GBatch batch,
    const float* __restrict__ b1_1, const float* __restrict__ b2_0,
    const float* __restrict__ b2_1, const float* __restrict__ W1_1,
    const float* __restrict__ W_out, const float* __restrict__ b_out,
    float* __restrict__ bu2, float* __restrict__ bo)
{
    __shared__ float As[16][65];
    __shared__ float Bs[16][64];
    int z = blockIdx.z;
    if (z < 5) {
        GJob jb = batch.j[z];
        if ((int)blockIdx.x * 64 >= jb.N || (int)blockIdx.y * 64 >= jb.M) return;
        sgemm64_body(jb.A, jb.B, jb.C, jb.M, jb.N, jb.K, jb.bias, jb.add, As, Bs);
        return;
    }
    int blkLin = blockIdx.y * 8 + blockIdx.x;
    int j = threadIdx.x;
    if (blkLin < 2) {
        int jj = blkLin * 256 + j;
        float s = b1_1[jj];
        for (int i = 0; i < 256; i++) s += b2_0[i] * W1_1[(size_t)i * 512 + jj];
        bu2[jj] = s;
    } else if (blkLin == 2) {
        float s = b_out[j];
        for (int i = 0; i < 256; i++) s += (b2_0[i] + b2_1[i]) * W_out[(size_t)i * 256 + j];
        bo[j] = s;
    }
}

__global__ __launch_bounds__(256) void sgemm64(
    const float* __restrict__ A, const float* __restrict__ B, float* __restrict__ C,
    int M, int N, int K, const float* __restrict__ bias, const float* __restrict__ add)
{
    __shared__ float As[16][65];
    __shared__ float Bs[16][64];
    sgemm64_body(A, B, C, M, N, K, bias, add, As, Bs);
}

// pack fp32 [512 k][N n] -> k64 chunks: [(n/128)*8+(k/64)][n%128][144B]
__device__ __forceinline__ void pack_body(const float* __restrict__ src,
                                          char* __restrict__ dst, int N, int idx)
{
    if (idx >= N * 256) return;
    int n = idx >> 8;
    int k = (idx & 255) * 2;
    float v0 = src[(size_t)k * N + n];
    float v1 = src[(size_t)(k + 1) * N + n];
    __half2 p = __floats2half2_rn(v0, v1);
    size_t off = (size_t)((n >> 7) * 8 + (k >> 6)) * CHUNK2 + (n & 127) * 144 + (k & 63) * 2;
    *(uint32_t*)(dst + off) = *(uint32_t*)&p;
}

__global__ __launch_bounds__(256) void stage3_kernel(
    GBatch batch,
    const float* __restrict__ M12, char* __restrict__ M12p,
    const float* __restrict__ M1o, char* __restrict__ M1op,
    const float* __restrict__ M2o, char* __restrict__ M2op)
{
    __shared__ float As[16][65];
    __shared__ float Bs[16][64];
    int z = blockIdx.z;
    if (z < 6) {
        GJob jb = batch.j[z];
        if ((int)blockIdx.x * 64 >= jb.N || (int)blockIdx.y * 64 >= jb.M) return;
        sgemm64_body(jb.A, jb.B, jb.C, jb.M, jb.N, jb.K, jb.bias, jb.add, As, Bs);
        return;
    }
    int blkLin = blockIdx.y * 8 + blockIdx.x;
    int tid = threadIdx.x;
    #pragma unroll 1
    for (int i = 0; i < 8; i++) {
        int vb = blkLin * 8 + i;
        if (vb < 512)       pack_body(M12, M12p, 512, vb * 256 + tid);
        else if (vb < 768)  pack_body(M1o, M1op, 256, (vb - 512) * 256 + tid);
        else                pack_body(M2o, M2op, 256, (vb - 768) * 256 + tid);
    }
    if (blkLin == 0 && tid < Bb) { g_cnum[tid] = 0; g_best[tid] = ~0ull; }
}

// ---------------- mma distance kernel: m32 tiles, 2 CTAs/SM ----------------------
#define RS1 520
#define TS_A1T 0
#define TS_A2T 2048
#define TS_OTX 4096
#define TS_SD  5120
#define TS_MBF 5632
#define TS_MBE 5648
#define TS_R1  6144
#define TS_R2  39424
#define TS_WT0 72704
#define TS_WT1 91136
#define TS_TOTAL 109568

__device__ __forceinline__ const char* wchunk(const char* base, int tile, int kc)
{
    return base + (size_t)(tile * 8 + kc) * CHUNK2;
}

// acc[16] += A[32 x k64] @ Wchunk^T : per warp m16 x n32, 4 k16-steps
__device__ __forceinline__ void chunk_mma(float* __restrict__ acc, uint32_t aAddr, uint32_t bAddr)
{
    #pragma unroll
    for (int ks = 0; ks < 4; ks++) {
        uint32_t a0, a1, a2, a3;
        ldsm4(a0, a1, a2, a3, aAddr + ks * 32);
        uint32_t b0, b1, b2, b3, b4, b5, b6, b7;
        ldsm4(b0, b1, b2, b3, bAddr + ks * 32);
        ldsm4(b4, b5, b6, b7, bAddr + ks * 32 + 16 * 144);
        mma_f16(acc + 0,  a0, a1, a2, a3, b0, b1);
        mma_f16(acc + 4,  a0, a1, a2, a3, b2, b3);
        mma_f16(acc + 8,  a0, a1, a2, a3, b4, b5);
        mma_f16(acc + 12, a0, a1, a2, a3, b6, b7);
    }
}

#define STEP(ACC, AADDR, SRC, HAVE) do { \
    int cur = buf, oth = buf ^ 1; \
    if ((HAVE) && tid == 0) { \
        MBARRIER_WAIT_PARITY(sb + TS_MBE + oth * 8, epar[oth]); epar[oth] ^= 1; \
        MBARRIER_EXPECT_TX(sb + TS_MBF + oth * 8, CHUNK2); \
        bulk_copy(sb + (oth ? TS_WT1 : TS_WT0), (SRC), CHUNK2, sb + TS_MBF + oth * 8); \
    } \
    MBARRIER_WAIT_PARITY(sb + TS_MBF + cur * 8, fpar[cur]); fpar[cur] ^= 1; \
    chunk_mma((ACC), (AADDR), (cur ? sb + TS_WT1 : sb + TS_WT0) + bOff); \
    MBARRIER_ARRIVE(sb + TS_MBE + cur * 8); \
    buf ^= 1; \
} while (0)

__global__ __launch_bounds__(256, 2) void dist_mma4_kernel(const float* __restrict__ x)
{
    extern __shared__ char smch[];
    const uint32_t sb = smem_to_u32(smch);
    float* a1t = (float*)(smch + TS_A1T);
    float* a2t = (float*)(smch + TS_A2T);
    float* otx = (float*)(smch + TS_OTX);
    float* sd  = (float*)(smch + TS_SD);

    const int bx = blockIdx.x;
    const int bf = bx >> 3, m0 = (bx & 7) * 32;
    const int b = bf >> 3, f = bf & 7;
    const int tid = threadIdx.x, lane = tid & 31, warp = tid >> 5;
    const int mw = warp & 1, ng = warp >> 1;
    const int g = lane >> 2, t = lane & 3;
    const int rowA = mw * 16 + g;        // 0..31
    const int ngbase = ng * 32;

    const uint32_t aOff = (uint32_t)(mw * 16 + (lane & 15)) * (RS1 * 2) + ((lane >> 4) & 1) * 16;
    const uint32_t aR1 = sb + TS_R1 + aOff;
    const uint32_t aR2 = sb + TS_R2 + aOff;
    const uint32_t bOff = (uint32_t)(ngbase + ((lane & 16) >> 1) + (lane & 7)) * 144
                        + ((lane & 8) >> 3) * 16;

    if (tid == 0) {
        MBARRIER_INIT(sb + TS_MBF,     1);
        MBARRIER_INIT(sb + TS_MBF + 8, 1);
        MBARRIER_INIT(sb + TS_MBE,     256);
        MBARRIER_INIT(sb + TS_MBE + 8, 256);
    }
    for (int i = tid; i < 512; i += 256) { a1t[i] = g_A1t[(size_t)bf*512 + i]; a2t[i] = g_A2t[(size_t)bf*512 + i]; }
    if (tid < 256) otx[tid] = g_Ot[(size_t)bf*256 + tid] - x[(size_t)b*256 + tid];
    __syncthreads();

    // R1 = relu(A1g[m0+r] + a1t)  -> [32][520] fp16
    for (int i = tid; i < 32 * 256; i += 256) {
        int r = i >> 8, c2 = i & 255;
        float2 av = *(const float2*)(g_A1g + (size_t)(m0 + r) * 512 + 2 * c2);
        float2 tv = *(const float2*)(a1t + 2 * c2);
        __half2 pk = __floats2half2_rn(fmaxf(av.x + tv.x, 0.f), fmaxf(av.y + tv.y, 0.f));
        *(uint32_t*)(smch + TS_R1 + ((size_t)r * RS1 + 2 * c2) * 2) = *(uint32_t*)&pk;
    }
    __syncthreads();

    int buf = 0;
    int fpar[2] = {0, 0};
    int epar[2] = {1, 1};
    if (tid == 0) {
        MBARRIER_WAIT_PARITY(sb + TS_MBE, epar[0]); epar[0] ^= 1;
        MBARRIER_EXPECT_TX(sb + TS_MBF, CHUNK2);
        bulk_copy(sb + TS_WT0, wchunk(g_M12p, 0, 0), CHUNK2, sb + TS_MBF);
    }

    float pr1 = 0.f, pr2 = 0.f;

    // ---- Phase A: u2 panels -> R2 ----
    for (int p = 0; p < 4; p++) {
        float u2[16];
        #pragma unroll
        for (int i = 0; i < 16; i++) u2[i] = 0.f;
        for (int c = 0; c < 8; c++) {
            const char* srcn;
            if (c < 7)      srcn = wchunk(g_M12p, p, c + 1);
            else if (p < 3) srcn = wchunk(g_M12p, p + 1, 0);
            else            srcn = wchunk(g_M1op, 0, 0);
            STEP(u2, aR1 + c * 128, srcn, 1);
        }
        #pragma unroll
        for (int j = 0; j < 4; j++) {
            int n = p * 128 + ngbase + j * 8 + 2 * t;
            float2 gv1 = *(const float2*)(g_A2g + (size_t)(m0 + rowA) * 512 + n);
            float2 gv2 = *(const float2*)(g_A2g + (size_t)(m0 + rowA + 8) * 512 + n);
            float2 tv  = *(const float2*)(a2t + n);
            __half2 q1 = __floats2half2_rn(fmaxf(u2[j*4+0] + gv1.x + tv.x, 0.f),
                                           fmaxf(u2[j*4+1] + gv1.y + tv.y, 0.f));
            __half2 q2 = __floats2half2_rn(fmaxf(u2[j*4+2] + gv2.x + tv.x, 0.f),
                                           fmaxf(u2[j*4+3] + gv2.y + tv.y, 0.f));
            *(uint32_t*)(smch + TS_R2 + ((size_t)rowA * RS1 + n) * 2)       = *(uint32_t*)&q1;
            *(uint32_t*)(smch + TS_R2 + ((size_t)(rowA + 8) * RS1 + n) * 2) = *(uint32_t*)&q2;
        }
    }
    __syncthreads();   // all R2 panels written before any warp reads aR2

    // ---- Phase B/C: corr halves ----
    #pragma unroll 1
    for (int h = 0; h < 2; h++) {
        float corr[16];
        #pragma unroll
        for (int i = 0; i < 16; i++) corr[i] = 0.f;
        const char* M1h = g_M1op;
        const char* M2h = g_M2op;
        for (int c = 0; c < 8; c++) {
            const char* srcn = (c < 7) ? wchunk(M1h, h, c + 1) : wchunk(M2h, h, 0);
            STEP(corr, aR1 + c * 128, srcn, 1);
        }
        for (int c = 0; c < 8; c++) {
            const char* srcn; int have = 1;
            if (c < 7)       srcn = wchunk(M2h, h, c + 1);
            else if (h == 0) srcn = wchunk(M1h, 1, 0);
            else           { srcn = nullptr; have = 0; }
            STEP(corr, aR2 + c * 128, srcn, have);
        }
        #pragma unroll
        for (int j = 0; j < 4; j++) {
            int n = h * 128 + ngbase + j * 8 + 2 * t;
            float2 og1 = *(const float2*)(g_Og + (size_t)(m0 + rowA) * 256 + n);
            float2 og2 = *(const float2*)(g_Og + (size_t)(m0 + rowA + 8) * 256 + n);
            float2 ox  = *(const float2*)(otx + n);
            float w;
            w = og1.x + ox.x + corr[j*4+0]; pr1 += w * w;
            w = og1.y + ox.y + corr[j*4+1]; pr1 += w * w;
            w = og2.x + ox.x + corr[j*4+2]; pr2 += w * w;
            w = og2.y + ox.y + corr[j*4+3]; pr2 += w * w;
        }
    }

    pr1 += __shfl_xor_sync(~0u, pr1, 1); pr1 += __shfl_xor_sync(~0u, pr1, 2);
    pr2 += __shfl_xor_sync(~0u, pr2, 1); pr2 += __shfl_xor_sync(~0u, pr2, 2);
    __syncthreads();
    if (t == 0) { sd[ng * 32 + rowA] = pr1; sd[ng * 32 + rowA + 8] = pr2; }
    __syncthreads();
    if (tid < 32)
        g_dists[(size_t)b * 2048 + f * 256 + m0 + tid] =
            sd[tid] + sd[32 + tid] + sd[64 + tid] + sd[96 + tid];
}

// ---------------- selection -----------------------------------------------------
__global__ __launch_bounds__(256) void selcollect_kernel()
{
    __shared__ float sv[256];
    int b = blockIdx.x, tid = threadIdx.x;
    float best = 3.4e38f;
    for (int i = tid; i < 2048; i += 256) best = fminf(best, g_dists[(size_t)b*2048 + i]);
    sv[tid] = best; __syncthreads();
    for (int s = 128; s > 0; s >>= 1) { if (tid < s) sv[tid] = fminf(sv[tid], sv[tid+s]); __syncthreads(); }
    float thr = sv[0] + DELTA;
    for (int i = tid; i < 2048; i += 256)
        if (g_dists[(size_t)b*2048 + i] <= thr) {
            int pos = atomicAdd(&g_cnum[b], 1);
            if (pos < CAND_CAP) g_clist[b*CAND_CAP + pos] = i;
        }
}

// ---------------- candidate-tiled exact rescore (verified R14) -------------------
__global__ __launch_bounds__(256) void rescore_kernel(const float* __restrict__ x)
{
    extern __shared__ float rs[];
    float* r1s = rs;
    float* r2s = rs + NC * 512;
    float* red = rs + 2 * NC * 512;
    __shared__ int kf[NC];

    const int b = blockIdx.x, tile = blockIdx.y, tid = threadIdx.x;
    int cnt = g_cnum[b]; if (cnt > CAND_CAP) cnt = CAND_CAP;
    const int base = tile * NC;
    if (base >= cnt) return;
    const int nc = min(NC, cnt - base);

    if (tid < NC)
        kf[tid] = g_clist[b * CAND_CAP + base + ((tid < nc) ? tid : 0)];
    __syncthreads();

    for (int c = 0; c < NC; c++) {
        int fi = kf[c], f = fi >> 8, k = fi & 255, bfi = b * 8 + f;
        for (int q = tid; q < 512; q += 256)
            r1s[c * 512 + q] = fmaxf(g_A1g[(size_t)k*512 + q] + g_A1t[(size_t)bfi*512 + q], 0.f);
    }
    __syncthreads();

    #pragma unroll 1
    for (int qq = 0; qq < 2; qq++) {
        const int q = tid + qq * 256;
        float s[NC];
        #pragma unroll
        for (int c = 0; c < NC; c++) s[c] = 0.f;
        #pragma unroll 1
        for (int i = 0; i < 512; i += 4) {
            float w0 = g_M12[(size_t)(i+0)*512 + q];
            float w1 = g_M12[(size_t)(i+1)*512 + q];
            float w2 = g_M12[(size_t)(i+2)*512 + q];
            float w3 = g_M12[(size_t)(i+3)*512 + q];
            #pragma unroll
            for (int c = 0; c < NC; c++) {
                float4 r = *(const float4*)(r1s + c * 512 + i);
                s[c] += r.x * w0; s[c] += r.y * w1; s[c] += r.z * w2; s[c] += r.w * w3;
            }
        }
        #pragma unroll
        for (int c = 0; c < NC; c++) {
            int fi = kf[c], f = fi >> 8, k = fi & 255, bfi = b * 8 + f;
            r2s[c * 512 + q] = fmaxf(g_A2g[(size_t)k*512 + q] + g_A2t[(size_t)bfi*512 + q] + s[c], 0.f);
        }
    }
    __syncthreads();

    float sq[NC];
    {
        const int d = tid;
        float corr[NC];
        #pragma unroll
        for (int c = 0; c < NC; c++) corr[c] = 0.f;
        #pragma unroll 1
        for (int i = 0; i < 512; i += 4) {
            float w10 = g_M1o[(size_t)(i+0)*256 + d], w20 = g_M2o[(size_t)(i+0)*256 + d];
            float w11 = g_M1o[(size_t)(i+1)*256 + d], w21 = g_M2o[(size_t)(i+1)*256 + d];
            float w12 = g_M1o[(size_t)(i+2)*256 + d], w22 = g_M2o[(size_t)(i+2)*256 + d];
            float w13 = g_M1o[(size_t)(i+3)*256 + d], w23 = g_M2o[(size_t)(i+3)*256 + d];
            #pragma unroll
            for (int c = 0; c < NC; c++) {
                float4 a = *(const float4*)(r1s + c * 512 + i);
                float4 bb = *(const float4*)(r2s + c * 512 + i);
                corr[c] += a.x * w10; corr[c] += bb.x * w20;
                corr[c] += a.y * w11; corr[c] += bb.y * w21;
                corr[c] += a.z * w12; corr[c] += bb.z * w22;
                corr[c] += a.w * w13; corr[c] += bb.w * w23;
            }
        }
        #pragma unroll
        for (int c = 0; c < NC; c++) {
            int fi = kf[c], f = fi >> 8, k = fi & 255, bfi = b * 8 + f;
            float v = g_Og[(size_t)k*256 + d] + g_Ot[(size_t)bfi*256 + d] - x[(size_t)b*256 + d] + corr[c];
            sq[c] = v * v;
        }
    }
    for (int c = 0; c < nc; c++) {
        red[tid] = sq[c];
        __syncthreads();
        for (int s2 = 128; s2 > 0; s2 >>= 1) {
            if (tid < s2) red[tid] += red[tid + s2];
            __syncthreads();
        }
        if (tid == 0) {
            ull key = ((ull)__float_as_uint(red[0]) << 32) | (uint32_t)kf[c];
            atomicMin(&g_best[b], key);
        }
        __syncthreads();
    }
}

__global__ __launch_bounds__(512) void final_kernel(float* __restrict__ out)
{
    __shared__ float r1[512], r2[512];
    __shared__ int sIdx;
    int b = blockIdx.x, tid = threadIdx.x;
    if (tid == 0) sIdx = (int)(g_best[b] & 0xffffffffu);
    __syncthreads();
    int idx = sIdx, f = idx >> 8, k = idx & 255, bf = b*8 + f;
    r1[tid] = fmaxf(g_A1g[(size_t)k*512 + tid] + g_A1t[(size_t)bf*512 + tid], 0.f);
    __syncthreads();
    {
        float s = g_A2g[(size_t)k*512 + tid] + g_A2t[(size_t)bf*512 + tid];
        for (int i = 0; i < 512; i++) s += r1[i] * g_M12[(size_t)i*512 + tid];
        r2[tid] = fmaxf(s, 0.f);
    }
    __syncthreads();
    if (tid < 256) {
        float s = g_Og[(size_t)k*256 + tid] + g_Ot[(size_t)bf*256 + tid];
        for (int i = 0; i < 512; i++)
            s += r1[i] * g_M1o[(size_t)i*256 + tid] + r2[i] * g_M2o[(size_t)i*256 + tid];
        out[b*256 + tid] = s;
    }
}

__global__ void codes_kernel(const int* __restrict__ codes, float* __restrict__ out)
{
    int t = threadIdx.x;
    float* oc = out + Bb * Dd;
    if (t < 256)      oc[t] = (float)codes[t];
    else if (t < 384) oc[t] = (float)(g_best[t - 256] & 0xffffffffu);
}

// ---------------- launch --------------------------------------------------------
extern "C" void kernel_launch(void* const* d_in, const int* in_sizes, int n_in,
                              void* d_out, int out_size)
{
    const float* x        = (const float*)d_in[0];
    const float* xhat     = (const float*)d_in[1];
    const int*   codes    = (const int*)d_in[2];
    const float* codebook = (const float*)d_in[3];
    const float* W_in     = (const float*)d_in[4];
    const float* b_in     = (const float*)d_in[5];
    const float* W_cat    = (const float*)d_in[6];
    const float* b_cat    = (const float*)d_in[7];
    const float* W1       = (const float*)d_in[8];
    const float* b1       = (const float*)d_in[9];
    const float* W2       = (const float*)d_in[10];
    const float* b2       = (const float*)d_in[11];
    const float* W_out    = (const float*)d_in[12];
    const float* b_out    = (const float*)d_in[13];
    float* out = (float*)d_out;

    float *p_h0,*p_g,*p_t,*p_A1g,*p_A2g,*p_A1t,*p_A2t,*p_Og,*p_Ot,*p_M12,*p_M1o,*p_M2o,*p_bu2,*p_bo;
    char *p_M12p, *p_M1op, *p_M2op;
    cudaGetSymbolAddress((void**)&p_h0,  g_h0);
    cudaGetSymbolAddress((void**)&p_g,   g_g);
    cudaGetSymbolAddress((void**)&p_t,   g_t);
    cudaGetSymbolAddress((void**)&p_A1g, g_A1g);
    cudaGetSymbolAddress((void**)&p_A2g, g_A2g);
    cudaGetSymbolAddress((void**)&p_A1t, g_A1t);
    cudaGetSymbolAddress((void**)&p_A2t, g_A2t);
    cudaGetSymbolAddress((void**)&p_Og,  g_Og);
    cudaGetSymbolAddress((void**)&p_Ot,  g_Ot);
    cudaGetSymbolAddress((void**)&p_M12, g_M12);
    cudaGetSymbolAddress((void**)&p_M1o, g_M1o);
    cudaGetSymbolAddress((void**)&p_M2o, g_M2o);
    cudaGetSymbolAddress((void**)&p_bu2, g_bu2);
    cudaGetSymbolAddress((void**)&p_bo,  g_bo);
    cudaGetSymbolAddress((void**)&p_M12p, g_M12p);
    cudaGetSymbolAddress((void**)&p_M1op, g_M1op);
    cudaGetSymbolAddress((void**)&p_M2op, g_M2op);

    const float* W1_0 = W1;     const float* W1_1 = W1 + 256*512;
    const float* W2_0 = W2;     const float* W2_1 = W2 + 512*256;
    const float* Wc   = W_cat;  const float* Wx   = W_cat + 256*256;
    const float* b1_1 = b1 + 512;
    const float* b2_0 = b2;     const float* b2_1 = b2 + 256;

    GBatch s1 = {};
    s1.j[0] = { codebook, W_in,  p_h0,  256,  256, 256, b_in,  nullptr };
    s1.j[1] = { xhat,     Wx,    p_t,   1024, 256, 256, b_cat, nullptr };
    s1.j[2] = { W2_0,     W1_1,  p_M12, 512,  512, 256, nullptr, nullptr };
    s1.j[3] = { W2_0,     W_out, p_M1o, 512,  256, 256, nullptr, nullptr };
    s1.j[4] = { W2_1,     W_out, p_M2o, 512,  256, 256, nullptr, nullptr };
    stage1_kernel<<<dim3(8, 16, 6), 256>>>(s1, b1_1, b2_0, b2_1, W1_1, W_out, b_out, p_bu2, p_bo);

    sgemm64<<<dim3(4, 4), 256>>>(p_h0, Wc, p_g, 256, 256, 256, nullptr, nullptr);

    GBatch s3 = {};
    s3.j[0] = { p_g, W1_0,  p_A1g, 256,  512, 256, nullptr, nullptr };
    s3.j[1] = { p_t, W1_0,  p_A1t, 1024, 512, 256, b1,      nullptr };
    s3.j[2] = { p_g, W1_1,  p_A2g, 256,  512, 256, nullptr, nullptr };
    s3.j[3] = { p_t, W1_1,  p_A2t, 1024, 512, 256, p_bu2,   nullptr };
    s3.j[4] = { p_g, W_out, p_Og,  256,  256, 256, nullptr, codebook };
    s3.j[5] = { p_t, W_out, p_Ot,  1024, 256, 256, p_bo,    xhat };
    stage3_kernel<<<dim3(8, 16, 7), 256>>>(s3, p_M12, p_M12p, p_M1o, p_M1op, p_M2o, p_M2op);

    cudaFuncSetAttribute(dist_mma4_kernel, cudaFuncAttributeMaxDynamicSharedMemorySize, TS_TOTAL);
    dist_mma4_kernel<<<Bb * Ff * 8, 256, TS_TOTAL>>>(x);

    selcollect_kernel<<<Bb, 256>>>();

    const int rs_smem = (2 * NC * 512 + 256) * (int)sizeof(float);
    cudaFuncSetAttribute(rescore_kernel, cudaFuncAttributeMaxDynamicSharedMemorySize, rs_smem);
    rescore_kernel<<<dim3(Bb, CAND_CAP / NC), 256, rs_smem>>>(x);

    final_kernel<<<Bb, 512>>>(out);
    codes_kernel<<<1, 384>>>(codes, out);
}

// round 16
// speedup vs baseline: 1.1103x; 1.1103x over previous
#include <cuda_runtime.h>
#include <cuda_fp16.h>
#include <cstdint>

#define Bb 128
#define Ff 8
#define Kk 256
#define Dd 256
#define Hh 256
#define HFF 512
#define CAND_CAP 512
#define DELTA 0.75f
#define NC 16
#define CHUNK_BYTES 34816   // 128 n-rows x 272B (k128 fp16 + 16B pad)
typedef unsigned long long ull;

// ---------------- device scratch ---------------------------------------------
__device__ float g_h0 [Kk*Hh];
__device__ float g_g  [Kk*Hh];
__device__ float g_t  [Bb*Ff*Hh];
__device__ float g_A1g[Kk*HFF];
__device__ float g_A2g[Kk*HFF];
__device__ float g_A1t[Bb*Ff*HFF];
__device__ float g_A2t[Bb*Ff*HFF];
__device__ float g_Og [Kk*Dd];
__device__ float g_Ot [Bb*Ff*Dd];
__device__ float g_M12[HFF*HFF];
__device__ float g_M1o[HFF*Dd];
__device__ float g_M2o[HFF*Dd];
__device__ float g_bu2[HFF];
__device__ float g_bo [Dd];
__device__ float g_dists[Bb*Ff*Kk];
__device__ __align__(128) char g_M12p[16*CHUNK_BYTES];
__device__ __align__(128) char g_M1op[ 8*CHUNK_BYTES];
__device__ __align__(128) char g_M2op[ 8*CHUNK_BYTES];
__device__ int  g_cnum[Bb];
__device__ int  g_clist[Bb*CAND_CAP];
__device__ ull  g_best[Bb];

// ---------------- helpers ------------------------------------------------------
__device__ __forceinline__ uint32_t smem_to_u32(const void* p) {
    uint32_t a;
    asm("{ .reg .u64 t; cvta.to.shared.u64 t, %1; cvt.u32.u64 %0, t; }" : "=r"(a) : "l"(p));
    return a;
}
__device__ __forceinline__ void mma_f16(float* c, uint32_t a0, uint32_t a1, uint32_t a2,
                                        uint32_t a3, uint32_t b0, uint32_t b1)
{
    asm volatile(
        "mma.sync.aligned.m16n8k16.row.col.f32.f16.f16.f32 "
        "{%0,%1,%2,%3}, {%4,%5,%6,%7}, {%8,%9}, {%0,%1,%2,%3};"
        : "+f"(c[0]), "+f"(c[1]), "+f"(c[2]), "+f"(c[3])
        : "r"(a0), "r"(a1), "r"(a2), "r"(a3), "r"(b0), "r"(b1));
}
__device__ __forceinline__ void ldsm4(uint32_t& r0, uint32_t& r1, uint32_t& r2, uint32_t& r3,
                                      uint32_t addr)
{
    asm volatile("ldmatrix.sync.aligned.m8n8.x4.shared.b16 {%0,%1,%2,%3}, [%4];"
        : "=r"(r0), "=r"(r1), "=r"(r2), "=r"(r3) : "r"(addr));
}
#define MBARRIER_INIT(addr, cnt) \
    asm volatile("mbarrier.init.shared.b64 [%0], %1;" :: "r"((uint32_t)(addr)), "r"((uint32_t)(cnt)) : "memory")
#define MBARRIER_ARRIVE(addr) \
    asm volatile("mbarrier.arrive.shared.b64 _, [%0];" :: "r"((uint32_t)(addr)) : "memory")
#define MBARRIER_EXPECT_TX(addr, tx) \
    asm volatile("mbarrier.arrive.expect_tx.shared.b64 _, [%0], %1;" :: "r"((uint32_t)(addr)), "r"((uint32_t)(tx)) : "memory")
#define MBARRIER_WAIT_PARITY(addr, par) do { \
    uint32_t _mb = (uint32_t)(addr); uint32_t _p = (uint32_t)(par); uint32_t _d; \
    asm volatile("{\n\t.reg .pred p;\n\t" \
        "mbarrier.try_wait.parity.acquire.cta.shared::cta.b64 p, [%1], %2;\n\t" \
        "selp.b32 %0, 1, 0, p;\n\t}" : "=r"(_d) : "r"(_mb), "r"(_p) : "memory"); \
    if (!_d) { \
        asm volatile("{\n\t.reg .pred P1;\n\t" \
            "WL_%=:\n\t" \
            "mbarrier.try_wait.parity.acquire.cta.shared::cta.b64 P1, [%0], %1, 0x989680;\n\t" \
            "@P1 bra.uni WD_%=;\n\t" \
            "bra.uni WL_%=;\n\t" \
            "WD_%=:\n\t}" :: "r"(_mb), "r"(_p) : "memory"); \
    } } while (0)
__device__ __forceinline__ void bulk_copy(uint32_t dst_smem, const void* src, uint32_t bytes,
                                          uint32_t mbar)
{
    asm volatile(
        "cp.async.bulk.shared::cluster.global.mbarrier::complete_tx::bytes [%0], [%1], %2, [%3];"
        :: "r"(dst_smem), "l"(src), "r"(bytes), "r"(mbar) : "memory");
}

// ---------------- batched precompute --------------------------------------------
struct GJob { const float* A; const float* B; float* C; int M, N, K;
              const float* bias; const float* add; };
struct GBatch { GJob j[6]; };

__device__ __forceinline__ void sgemm64_body(
    const float* __restrict__ A, const float* __restrict__ B, float* __restrict__ C,
    int M, int N, int K, const float* __restrict__ bias, const float* __restrict__ add,
    float As[16][65], float Bs[16][64])
{
    const int m0 = blockIdx.y * 64, n0 = blockIdx.x * 64;
    const int tid = threadIdx.x, tx = tid & 15, ty = tid >> 4;
    float acc[4][4] = {};
    for (int k0 = 0; k0 < K; k0 += 16) {
        int ra = tid >> 2, ca = (tid & 3) * 4;
        float4 av = *(const float4*)(A + (size_t)(m0 + ra) * K + k0 + ca);
        As[ca+0][ra] = av.x; As[ca+1][ra] = av.y; As[ca+2][ra] = av.z; As[ca+3][ra] = av.w;
        int rb = tid >> 4, cb = (tid & 15) * 4;
        *(float4*)&Bs[rb][cb] = *(const float4*)(B + (size_t)(k0 + rb) * N + n0 + cb);
        __syncthreads();
        #pragma unroll
        for (int kk = 0; kk < 16; kk++) {
            float a0 = As[kk][ty*4+0], a1 = As[kk][ty*4+1];
            float a2 = As[kk][ty*4+2], a3 = As[kk][ty*4+3];
            float4 bv = *(float4*)&Bs[kk][tx*4];
            acc[0][0]+=a0*bv.x; acc[0][1]+=a0*bv.y; acc[0][2]+=a0*bv.z; acc[0][3]+=a0*bv.w;
            acc[1][0]+=a1*bv.x; acc[1][1]+=a1*bv.y; acc[1][2]+=a1*bv.z; acc[1][3]+=a1*bv.w;
            acc[2][0]+=a2*bv.x; acc[2][1]+=a2*bv.y; acc[2][2]+=a2*bv.z; acc[2][3]+=a2*bv.w;
            acc[3][0]+=a3*bv.x; acc[3][1]+=a3*bv.y; acc[3][2]+=a3*bv.z; acc[3][3]+=a3*bv.w;
        }
        __syncthreads();
    }
    #pragma unroll
    for (int i = 0; i < 4; i++)
        #pragma unroll
        for (int j = 0; j < 4; j++) {
            int m = m0 + ty*4 + i, n = n0 + tx*4 + j;
            float v = acc[i][j];
            if (bias) v += bias[n];
            if (add)  v += add[(size_t)m * N + n];
            C[(size_t)m * N + n] = v;
        }
}

__global__ __launch_bounds__(256) void stage1_kernel(
    GBatch batch,
    const float* __restrict__ b1_1, const float* __restrict__ b2_0,
    const float* __restrict__ b2_1, const float* __restrict__ W1_1,
    const float* __restrict__ W_out, const float* __restrict__ b_out,
    float* __restrict__ bu2, float* __restrict__ bo)
{
    __shared__ float As[16][65];
    __shared__ float Bs[16][64];
    int z = blockIdx.z;
    if (z < 5) {
        GJob jb = batch.j[z];
        if ((int)blockIdx.x * 64 >= jb.N || (int)blockIdx.y * 64 >= jb.M) return;
        sgemm64_body(jb.A, jb.B, jb.C, jb.M, jb.N, jb.K, jb.bias, jb.add, As, Bs);
        return;
    }
    int blkLin = blockIdx.y * 8 + blockIdx.x;
    int j = threadIdx.x;
    if (blkLin < 2) {
        int jj = blkLin * 256 + j;
        float s = b1_1[jj];
        for (int i = 0; i < 256; i++) s += b2_0[i] * W1_1[(size_t)i * 512 + jj];
        bu2[jj] = s;
    } else if (blkLin == 2) {
        float s = b_out[j];
        for (int i = 0; i < 256; i++) s += (b2_0[i] + b2_1[i]) * W_out[(size_t)i * 256 + j];
        bo[j] = s;
    }
}

__global__ __launch_bounds__(256) void sgemm64(
    const float* __restrict__ A, const float* __restrict__ B, float* __restrict__ C,
    int M, int N, int K, const float* __restrict__ bias, const float* __restrict__ add)
{
    __shared__ float As[16][65];
    __shared__ float Bs[16][64];
    sgemm64_body(A, B, C, M, N, K, bias, add, As, Bs);
}

__device__ __forceinline__ void pack_body(const float* __restrict__ src,
                                          char* __restrict__ dst, int N, int idx)
{
    if (idx >= N * 256) return;
    int n = idx >> 8;
    int k = (idx & 255) * 2;
    float v0 = src[(size_t)k * N + n];
    float v1 = src[(size_t)(k + 1) * N + n];
    __half2 p = __floats2half2_rn(v0, v1);
    size_t off = (size_t)((n >> 7) * 4 + (k >> 7)) * CHUNK_BYTES + (n & 127) * 272 + (k & 127) * 2;
    *(uint32_t*)(dst + off) = *(uint32_t*)&p;
}

__global__ __launch_bounds__(256) void stage3_kernel(
    GBatch batch,
    const float* __restrict__ M12, char* __restrict__ M12p,
    const float* __restrict__ M1o, char* __restrict__ M1op,
    const float* __restrict__ M2o, char* __restrict__ M2op)
{
    __shared__ float As[16][65];
    __shared__ float Bs[16][64];
    int z = blockIdx.z;
    if (z < 6) {
        GJob jb = batch.j[z];
        if ((int)blockIdx.x * 64 >= jb.N || (int)blockIdx.y * 64 >= jb.M) return;
        sgemm64_body(jb.A, jb.B, jb.C, jb.M, jb.N, jb.K, jb.bias, jb.add, As, Bs);
        return;
    }
    int blkLin = blockIdx.y * 8 + blockIdx.x;
    int tid = threadIdx.x;
    #pragma unroll 1
    for (int i = 0; i < 8; i++) {
        int vb = blkLin * 8 + i;
        if (vb < 512)       pack_body(M12, M12p, 512, vb * 256 + tid);
        else if (vb < 768)  pack_body(M1o, M1op, 256, (vb - 512) * 256 + tid);
        else                pack_body(M2o, M2op, 256, (vb - 768) * 256 + tid);
    }
    if (blkLin == 0 && tid < Bb) { g_cnum[tid] = 0; g_best[tid] = ~0ull; }
}

// ---------------- mma distance kernel: m64 tile, mw2 x ng4 warps ------------------
#define RS1 520
#define TS_A1T 0
#define TS_A2T 2048
#define TS_OTX 4096
#define TS_MBF 5120
#define TS_MBE 5136
#define TS_R1  6144
#define TS_R2  72704
#define TS_WT0 139264
#define TS_WT1 174080
#define TS_TOTAL 208896

__device__ __forceinline__ const char* wchunk(const char* base, int tile, int cn)
{
    return base + (size_t)(tile * 4 + cn) * CHUNK_BYTES;
}

// acc[32] += A[m32 x k128] @ Wchunk[n32]^T : per warp m32 x n32.
// acc layout: [ma*16 + j*4 + c], ma = m-atom (rows +0/+16), j = n-atom.
__device__ __forceinline__ void chunk_mma(float* __restrict__ acc, uint32_t aAddr, uint32_t bAddr)
{
    #pragma unroll
    for (int ks = 0; ks < 8; ks++) {
        uint32_t a0, a1, a2, a3, a4, a5, a6, a7;
        ldsm4(a0, a1, a2, a3, aAddr + ks * 32);
        ldsm4(a4, a5, a6, a7, aAddr + ks * 32 + 16 * (RS1 * 2));
        uint32_t b0, b1, b2, b3, b4, b5, b6, b7;
        ldsm4(b0, b1, b2, b3, bAddr + ks * 32);
        ldsm4(b4, b5, b6, b7, bAddr + ks * 32 + 16 * 272);
        mma_f16(acc + 0,  a0, a1, a2, a3, b0, b1);
        mma_f16(acc + 4,  a0, a1, a2, a3, b2, b3);
        mma_f16(acc + 8,  a0, a1, a2, a3, b4, b5);
        mma_f16(acc + 12, a0, a1, a2, a3, b6, b7);
        mma_f16(acc + 16, a4, a5, a6, a7, b0, b1);
        mma_f16(acc + 20, a4, a5, a6, a7, b2, b3);
        mma_f16(acc + 24, a4, a5, a6, a7, b4, b5);
        mma_f16(acc + 28, a4, a5, a6, a7, b6, b7);
    }
}

#define STEP(ACC, AADDR, SRC, HAVE) do { \
    int cur = buf, oth = buf ^ 1; \
    if ((HAVE) && tid == 0) { \
        MBARRIER_WAIT_PARITY(sb + TS_MBE + oth * 8, epar[oth]); epar[oth] ^= 1; \
        MBARRIER_EXPECT_TX(sb + TS_MBF + oth * 8, CHUNK_BYTES); \
        bulk_copy(sb + (oth ? TS_WT1 : TS_WT0), (SRC), CHUNK_BYTES, sb + TS_MBF + oth * 8); \
    } \
    MBARRIER_WAIT_PARITY(sb + TS_MBF + cur * 8, fpar[cur]); fpar[cur] ^= 1; \
    chunk_mma((ACC), (AADDR), (cur ? sb + TS_WT1 : sb + TS_WT0) + bOff); \
    MBARRIER_ARRIVE(sb + TS_MBE + cur * 8); \
    buf ^= 1; \
} while (0)

__global__ __launch_bounds__(256, 1) void dist_mma5_kernel(const float* __restrict__ x)
{
    extern __shared__ char smch[];
    const uint32_t sb = smem_to_u32(smch);
    float* a1t = (float*)(smch + TS_A1T);
    float* a2t = (float*)(smch + TS_A2T);
    float* otx = (float*)(smch + TS_OTX);

    const int bx = blockIdx.x;
    const int bf = bx >> 2, m0 = (bx & 3) * 64;
    const int b = bf >> 3, f = bf & 7;
    const int tid = threadIdx.x, lane = tid & 31, warp = tid >> 5;
    const int mw = warp & 1, ng = warp >> 1;      // mw2 x ng4
    const int g = lane >> 2, t = lane & 3;
    const int rowW = mw * 32;                     // warp's m base (0 or 32)
    const int ngbase = ng * 32;

    const uint32_t aOff = (uint32_t)(rowW + (lane & 15)) * (RS1 * 2) + ((lane >> 4) & 1) * 16;
    const uint32_t aR1 = sb + TS_R1 + aOff;
    const uint32_t aR2 = sb + TS_R2 + aOff;
    const uint32_t bOff = (uint32_t)(ngbase + ((lane & 16) >> 1) + (lane & 7)) * 272
                        + ((lane & 8) >> 3) * 16;

    if (tid == 0) {
        MBARRIER_INIT(sb + TS_MBF,     1);
        MBARRIER_INIT(sb + TS_MBF + 8, 1);
        MBARRIER_INIT(sb + TS_MBE,     256);
        MBARRIER_INIT(sb + TS_MBE + 8, 256);
    }
    for (int i = tid; i < 512; i += 256) { a1t[i] = g_A1t[(size_t)bf*512 + i]; a2t[i] = g_A2t[(size_t)bf*512 + i]; }
    if (tid < 256) otx[tid] = g_Ot[(size_t)bf*256 + tid] - x[(size_t)b*256 + tid];
    __syncthreads();

    for (int i = tid; i < 64 * 256; i += 256) {
        int r = i >> 8, c2 = i & 255;
        float2 av = *(const float2*)(g_A1g + (size_t)(m0 + r) * 512 + 2 * c2);
        float2 tv = *(const float2*)(a1t + 2 * c2);
        __half2 pk = __floats2half2_rn(fmaxf(av.x + tv.x, 0.f), fmaxf(av.y + tv.y, 0.f));
        *(uint32_t*)(smch + TS_R1 + ((size_t)r * RS1 + 2 * c2) * 2) = *(uint32_t*)&pk;
    }
    __syncthreads();

    int buf = 0;
    int fpar[2] = {0, 0};
    int epar[2] = {1, 1};
    if (tid == 0) {
        MBARRIER_WAIT_PARITY(sb + TS_MBE, epar[0]); epar[0] ^= 1;
        MBARRIER_EXPECT_TX(sb + TS_MBF, CHUNK_BYTES);
        bulk_copy(sb + TS_WT0, wchunk(g_M12p, 0, 0), CHUNK_BYTES, sb + TS_MBF);
    }

    float pr[4] = {0.f, 0.f, 0.f, 0.f};   // [ma*2 + (row vs row+8)]

    // ---- Phase A: u2 panels -> R2 ----
    for (int p = 0; p < 4; p++) {
        float u2[32];
        #pragma unroll
        for (int i = 0; i < 32; i++) u2[i] = 0.f;
        for (int c = 0; c < 4; c++) {
            const char* srcn;
            if (c < 3)      srcn = wchunk(g_M12p, p, c + 1);
            else if (p < 3) srcn = wchunk(g_M12p, p + 1, 0);
            else            srcn = wchunk(g_M1op, 0, 0);
            STEP(u2, aR1 + c * 256, srcn, 1);
        }
        #pragma unroll
        for (int ma = 0; ma < 2; ma++) {
            int rb = rowW + ma * 16 + g;
            #pragma unroll
            for (int j = 0; j < 4; j++) {
                int n = p * 128 + ngbase + j * 8 + 2 * t;
                float2 gv1 = *(const float2*)(g_A2g + (size_t)(m0 + rb) * 512 + n);
                float2 gv2 = *(const float2*)(g_A2g + (size_t)(m0 + rb + 8) * 512 + n);
                float2 tv  = *(const float2*)(a2t + n);
                __half2 q1 = __floats2half2_rn(fmaxf(u2[ma*16 + j*4 + 0] + gv1.x + tv.x, 0.f),
                                               fmaxf(u2[ma*16 + j*4 + 1] + gv1.y + tv.y, 0.f));
                __half2 q2 = __floats2half2_rn(fmaxf(u2[ma*16 + j*4 + 2] + gv2.x + tv.x, 0.f),
                                               fmaxf(u2[ma*16 + j*4 + 3] + gv2.y + tv.y, 0.f));
                *(uint32_t*)(smch + TS_R2 + ((size_t)rb * RS1 + n) * 2)       = *(uint32_t*)&q1;
                *(uint32_t*)(smch + TS_R2 + ((size_t)(rb + 8) * RS1 + n) * 2) = *(uint32_t*)&q2;
            }
        }
    }
    __syncthreads();   // all R2 panels written before any warp reads aR2

    // ---- Phase B/C: corr halves ----
    #pragma unroll 1
    for (int h = 0; h < 2; h++) {
        float corr[32];
        #pragma unroll
        for (int i = 0; i < 32; i++) corr[i] = 0.f;
        for (int c = 0; c < 4; c++) {
            const char* srcn = (c < 3) ? wchunk(g_M1op, h, c + 1) : wchunk(g_M2op, h, 0);
            STEP(corr, aR1 + c * 256, srcn, 1);
        }
        for (int c = 0; c < 4; c++) {
            const char* srcn; int have = 1;
            if (c < 3)       srcn = wchunk(g_M2op, h, c + 1);
            else if (h == 0) srcn = wchunk(g_M1op, 1, 0);
            else           { srcn = nullptr; have = 0; }
            STEP(corr, aR2 + c * 256, srcn, have);
        }
        #pragma unroll
        for (int ma = 0; ma < 2; ma++) {
            int rb = rowW + ma * 16 + g;
            #pragma unroll
            for (int j = 0; j < 4; j++) {
                int n = h * 128 + ngbase + j * 8 + 2 * t;
                float2 og1 = *(const float2*)(g_Og + (size_t)(m0 + rb) * 256 + n);
                float2 og2 = *(const float2*)(g_Og + (size_t)(m0 + rb + 8) * 256 + n);
                float2 ox  = *(const float2*)(otx + n);
                float w;
                w = og1.x + ox.x + corr[ma*16 + j*4 + 0]; pr[ma*2]     += w * w;
                w = og1.y + ox.y + corr[ma*16 + j*4 + 1]; pr[ma*2]     += w * w;
                w = og2.x + ox.x + corr[ma*16 + j*4 + 2]; pr[ma*2 + 1] += w * w;
                w = og2.y + ox.y + corr[ma*16 + j*4 + 3]; pr[ma*2 + 1] += w * w;
            }
        }
    }

    #pragma unroll
    for (int i = 0; i < 4; i++) {
        pr[i] += __shfl_xor_sync(~0u, pr[i], 1);
        pr[i] += __shfl_xor_sync(~0u, pr[i], 2);
    }
    float* sd = (float*)(smch + TS_A1T);   // [4 ng][64 m]
    __syncthreads();
    if (t == 0) {
        sd[ng * 64 + rowW + g]      = pr[0];
        sd[ng * 64 + rowW + g + 8]  = pr[1];
        sd[ng * 64 + rowW + g + 16] = pr[2];
        sd[ng * 64 + rowW + g + 24] = pr[3];
    }
    __syncthreads();
    if (tid < 64)
        g_dists[(size_t)b * 2048 + f * 256 + m0 + tid] =
            sd[tid] + sd[64 + tid] + sd[128 + tid] + sd[192 + tid];
}

// ---------------- selection -----------------------------------------------------
__global__ __launch_bounds__(256) void selcollect_kernel()
{
    __shared__ float sv[256];
    int b = blockIdx.x, tid = threadIdx.x;
    float best = 3.4e38f;
    for (int i = tid; i < 2048; i += 256) best = fminf(best, g_dists[(size_t)b*2048 + i]);
    sv[tid] = best; __syncthreads();
    for (int s = 128; s > 0; s >>= 1) { if (tid < s) sv[tid] = fminf(sv[tid], sv[tid+s]); __syncthreads(); }
    float thr = sv[0] + DELTA;
    for (int i = tid; i < 2048; i += 256)
        if (g_dists[(size_t)b*2048 + i] <= thr) {
            int pos = atomicAdd(&g_cnum[b], 1);
            if (pos < CAND_CAP) g_clist[b*CAND_CAP + pos] = i;
        }
}

// ---------------- candidate-tiled exact rescore (verified R14) -------------------
__global__ __launch_bounds__(256) void rescore_kernel(const float* __restrict__ x)
{
    extern __shared__ float rs[];
    float* r1s = rs;
    float* r2s = rs + NC * 512;
    float* red = rs + 2 * NC * 512;
    __shared__ int kf[NC];

    const int b = blockIdx.x, tile = blockIdx.y, tid = threadIdx.x;
    int cnt = g_cnum[b]; if (cnt > CAND_CAP) cnt = CAND_CAP;
    const int base = tile * NC;
    if (base >= cnt) return;
    const int nc = min(NC, cnt - base);

    if (tid < NC)
        kf[tid] = g_clist[b * CAND_CAP + base + ((tid < nc) ? tid : 0)];
    __syncthreads();

    for (int c = 0; c < NC; c++) {
        int fi = kf[c], f = fi >> 8, k = fi & 255, bfi = b * 8 + f;
        for (int q = tid; q < 512; q += 256)
            r1s[c * 512 + q] = fmaxf(g_A1g[(size_t)k*512 + q] + g_A1t[(size_t)bfi*512 + q], 0.f);
    }
    __syncthreads();

    #pragma unroll 1
    for (int qq = 0; qq < 2; qq++) {
        const int q = tid + qq * 256;
        float s[NC];
        #pragma unroll
        for (int c = 0; c < NC; c++) s[c] = 0.f;
        #pragma unroll 1
        for (int i = 0; i < 512; i += 4) {
            float w0 = g_M12[(size_t)(i+0)*512 + q];
            float w1 = g_M12[(size_t)(i+1)*512 + q];
            float w2 = g_M12[(size_t)(i+2)*512 + q];
            float w3 = g_M12[(size_t)(i+3)*512 + q];
            #pragma unroll
            for (int c = 0; c < NC; c++) {
                float4 r = *(const float4*)(r1s + c * 512 + i);
                s[c] += r.x * w0; s[c] += r.y * w1; s[c] += r.z * w2; s[c] += r.w * w3;
            }
        }
        #pragma unroll
        for (int c = 0; c < NC; c++) {
            int fi = kf[c], f = fi >> 8, k = fi & 255, bfi = b * 8 + f;
            r2s[c * 512 + q] = fmaxf(g_A2g[(size_t)k*512 + q] + g_A2t[(size_t)bfi*512 + q] + s[c], 0.f);
        }
    }
    __syncthreads();

    float sq[NC];
    {
        const int d = tid;
        float corr[NC];
        #pragma unroll
        for (int c = 0; c < NC; c++) corr[c] = 0.f;
        #pragma unroll 1
        for (int i = 0; i < 512; i += 4) {
            float w10 = g_M1o[(size_t)(i+0)*256 + d], w20 = g_M2o[(size_t)(i+0)*256 + d];
            float w11 = g_M1o[(size_t)(i+1)*256 + d], w21 = g_M2o[(size_t)(i+1)*256 + d];
            float w12 = g_M1o[(size_t)(i+2)*256 + d], w22 = g_M2o[(size_t)(i+2)*256 + d];
            float w13 = g_M1o[(size_t)(i+3)*256 + d], w23 = g_M2o[(size_t)(i+3)*256 + d];
            #pragma unroll
            for (int c = 0; c < NC; c++) {
                float4 a = *(const float4*)(r1s + c * 512 + i);
                float4 bb = *(const float4*)(r2s + c * 512 + i);
                corr[c] += a.x * w10; corr[c] += bb.x * w20;
                corr[c] += a.y * w11; corr[c] += bb.y * w21;
                corr[c] += a.z * w12; corr[c] += bb.z * w22;
                corr[c] += a.w * w13; corr[c] += bb.w * w23;
            }
        }
        #pragma unroll
        for (int c = 0; c < NC; c++) {
            int fi = kf[c], f = fi >> 8, k = fi & 255, bfi = b * 8 + f;
            float v = g_Og[(size_t)k*256 + d] + g_Ot[(size_t)bfi*256 + d] - x[(size_t)b*256 + d] + corr[c];
            sq[c] = v * v;
        }
    }
    for (int c = 0; c < nc; c++) {
        red[tid] = sq[c];
        __syncthreads();
        for (int s2 = 128; s2 > 0; s2 >>= 1) {
            if (tid < s2) red[tid] += red[tid + s2];
            __syncthreads();
        }
        if (tid == 0) {
            ull key = ((ull)__float_as_uint(red[0]) << 32) | (uint32_t)kf[c];
            atomicMin(&g_best[b], key);
        }
        __syncthreads();
    }
}

__global__ __launch_bounds__(512) void final_kernel(float* __restrict__ out)
{
    __shared__ float r1[512], r2[512];
    __shared__ int sIdx;
    int b = blockIdx.x, tid = threadIdx.x;
    if (tid == 0) sIdx = (int)(g_best[b] & 0xffffffffu);
    __syncthreads();
    int idx = sIdx, f = idx >> 8, k = idx & 255, bf = b*8 + f;
    r1[tid] = fmaxf(g_A1g[(size_t)k*512 + tid] + g_A1t[(size_t)bf*512 + tid], 0.f);
    __syncthreads();
    {
        float s = g_A2g[(size_t)k*512 + tid] + g_A2t[(size_t)bf*512 + tid];
        for (int i = 0; i < 512; i++) s += r1[i] * g_M12[(size_t)i*512 + tid];
        r2[tid] = fmaxf(s, 0.f);
    }
    __syncthreads();
    if (tid < 256) {
        float s = g_Og[(size_t)k*256 + tid] + g_Ot[(size_t)bf*256 + tid];
        for (int i = 0; i < 512; i++)
            s += r1[i] * g_M1o[(size_t)i*256 + tid] + r2[i] * g_M2o[(size_t)i*256 + tid];
        out[b*256 + tid] = s;
    }
}

__global__ void codes_kernel(const int* __restrict__ codes, float* __restrict__ out)
{
    int t = threadIdx.x;
    float* oc = out + Bb * Dd;
    if (t < 256)      oc[t] = (float)codes[t];
    else if (t < 384) oc[t] = (float)(g_best[t - 256] & 0xffffffffu);
}

// ---------------- launch --------------------------------------------------------
extern "C" void kernel_launch(void* const* d_in, const int* in_sizes, int n_in,
                              void* d_out, int out_size)
{
    const float* x        = (const float*)d_in[0];
    const float* xhat     = (const float*)d_in[1];
    const int*   codes    = (const int*)d_in[2];
    const float* codebook = (const float*)d_in[3];
    const float* W_in     = (const float*)d_in[4];
    const float* b_in     = (const float*)d_in[5];
    const float* W_cat    = (const float*)d_in[6];
    const float* b_cat    = (const float*)d_in[7];
    const float* W1       = (const float*)d_in[8];
    const float* b1       = (const float*)d_in[9];
    const float* W2       = (const float*)d_in[10];
    const float* b2       = (const float*)d_in[11];
    const float* W_out    = (const float*)d_in[12];
    const float* b_out    = (const float*)d_in[13];
    float* out = (float*)d_out;

    float *p_h0,*p_g,*p_t,*p_A1g,*p_A2g,*p_A1t,*p_A2t,*p_Og,*p_Ot,*p_M12,*p_M1o,*p_M2o,*p_bu2,*p_bo;
    char *p_M12p, *p_M1op, *p_M2op;
    cudaGetSymbolAddress((void**)&p_h0,  g_h0);
    cudaGetSymbolAddress((void**)&p_g,   g_g);
    cudaGetSymbolAddress((void**)&p_t,   g_t);
    cudaGetSymbolAddress((void**)&p_A1g, g_A1g);
    cudaGetSymbolAddress((void**)&p_A2g, g_A2g);
    cudaGetSymbolAddress((void**)&p_A1t, g_A1t);
    cudaGetSymbolAddress((void**)&p_A2t, g_A2t);
    cudaGetSymbolAddress((void**)&p_Og,  g_Og);
    cudaGetSymbolAddress((void**)&p_Ot,  g_Ot);
    cudaGetSymbolAddress((void**)&p_M12, g_M12);
    cudaGetSymbolAddress((void**)&p_M1o, g_M1o);
    cudaGetSymbolAddress((void**)&p_M2o, g_M2o);
    cudaGetSymbolAddress((void**)&p_bu2, g_bu2);
    cudaGetSymbolAddress((void**)&p_bo,  g_bo);
    cudaGetSymbolAddress((void**)&p_M12p, g_M12p);
    cudaGetSymbolAddress((void**)&p_M1op, g_M1op);
    cudaGetSymbolAddress((void**)&p_M2op, g_M2op);

    const float* W1_0 = W1;     const float* W1_1 = W1 + 256*512;
    const float* W2_0 = W2;     const float* W2_1 = W2 + 512*256;
    const float* Wc   = W_cat;  const float* Wx   = W_cat + 256*256;
    const float* b1_1 = b1 + 512;
    const float* b2_0 = b2;     const float* b2_1 = b2 + 256;

    GBatch s1 = {};
    s1.j[0] = { codebook, W_in,  p_h0,  256,  256, 256, b_in,  nullptr };
    s1.j[1] = { xhat,     Wx,    p_t,   1024, 256, 256, b_cat, nullptr };
    s1.j[2] = { W2_0,     W1_1,  p_M12, 512,  512, 256, nullptr, nullptr };
    s1.j[3] = { W2_0,     W_out, p_M1o, 512,  256, 256, nullptr, nullptr };
    s1.j[4] = { W2_1,     W_out, p_M2o, 512,  256, 256, nullptr, nullptr };
    stage1_kernel<<<dim3(8, 16, 6), 256>>>(s1, b1_1, b2_0, b2_1, W1_1, W_out, b_out, p_bu2, p_bo);

    sgemm64<<<dim3(4, 4), 256>>>(p_h0, Wc, p_g, 256, 256, 256, nullptr, nullptr);

    GBatch s3 = {};
    s3.j[0] = { p_g, W1_0,  p_A1g, 256,  512, 256, nullptr, nullptr };
    s3.j[1] = { p_t, W1_0,  p_A1t, 1024, 512, 256, b1,      nullptr };
    s3.j[2] = { p_g, W1_1,  p_A2g, 256,  512, 256, nullptr, nullptr };
    s3.j[3] = { p_t, W1_1,  p_A2t, 1024, 512, 256, p_bu2,   nullptr };
    s3.j[4] = { p_g, W_out, p_Og,  256,  256, 256, nullptr, codebook };
    s3.j[5] = { p_t, W_out, p_Ot,  1024, 256, 256, p_bo,    xhat };
    stage3_kernel<<<dim3(8, 16, 7), 256>>>(s3, p_M12, p_M12p, p_M1o, p_M1op, p_M2o, p_M2op);

    cudaFuncSetAttribute(dist_mma5_kernel, cudaFuncAttributeMaxDynamicSharedMemorySize, TS_TOTAL);
    dist_mma5_kernel<<<Bb * Ff * 4, 256, TS_TOTAL>>>(x);

    selcollect_kernel<<<Bb, 256>>>();

    const int rs_smem = (2 * NC * 512 + 256) * (int)sizeof(float);
    cudaFuncSetAttribute(rescore_kernel, cudaFuncAttributeMaxDynamicSharedMemorySize, rs_smem);
    rescore_kernel<<<dim3(Bb, CAND_CAP / NC), 256, rs_smem>>>(x);

    final_kernel<<<Bb, 512>>>(out);
    codes_kernel<<<1, 384>>>(codes, out);
}